// round 6
// baseline (speedup 1.0000x reference)
#include <cuda_runtime.h>

// Problem dims
#define NB 256
#define NT 128
#define NS 12
#define NC 4
#define NM 6
#define MU_C 0.1f

// Output layout: flattened tuple (ku, Ku, ks, Ks, dV, opterr, Vx, Vxx), float32
#define O_ku   0
#define O_Ku   131072
#define O_ks   1703936
#define O_Ks   1900544
#define O_dV   4259840
#define O_opt  4260352
#define O_Vx   4260353
#define O_Vxx  4263425

// Stage (per-(b,t) input block) layout inside shared memory, in floats
#define SG_FXX 0       // 1728
#define SG_FXU 1728    // 576
#define SG_FUU 2304    // 192
#define SG_FX  2496    // 144
#define SG_QXX 2640    // 144
#define SG_FU  2784    // 48
#define SG_QXU 2832    // 48
#define SG_CX  2880    // 72
#define SG_CU  2952    // 24
#define SG_QUU 2976    // 16
#define SG_QX  2992    // 12
#define SG_QU  3004    // 4
#define SG_C   3008    // 6
#define SG_S   3014    // 6
#define SG_TOT 3020

__device__ __forceinline__ void cpa16(float* dst, const void* src) {
    unsigned ds = (unsigned)__cvta_generic_to_shared(dst);
    asm volatile("cp.async.ca.shared.global [%0], [%1], 16;" :: "r"(ds), "l"(src));
}
__device__ __forceinline__ void cpa4(float* dst, const void* src) {
    unsigned ds = (unsigned)__cvta_generic_to_shared(dst);
    asm volatile("cp.async.ca.shared.global [%0], [%1], 4;" :: "r"(ds), "l"(src));
}
__device__ __forceinline__ void cpa_commit() {
    asm volatile("cp.async.commit_group;");
}
__device__ __forceinline__ void cpa_wait_all() {
    asm volatile("cp.async.wait_group 0;");
}

__global__ void init_opt_kernel(float* out) { out[O_opt] = 0.0f; }

// One warp (32 threads) per batch. No block barriers; all sync is __syncwarp.
__global__ void __launch_bounds__(32, 4) ddp_backward_kernel(
    const float* __restrict__ g_qx,  const float* __restrict__ g_qu,
    const float* __restrict__ g_qxx, const float* __restrict__ g_qxu,
    const float* __restrict__ g_quu, const float* __restrict__ g_fx,
    const float* __restrict__ g_fu,  const float* __restrict__ g_fxx,
    const float* __restrict__ g_fxu, const float* __restrict__ g_fuu,
    const float* __restrict__ g_cx,  const float* __restrict__ g_cu,
    const float* __restrict__ g_c,   const float* __restrict__ g_s,
    const float* __restrict__ g_px,  const float* __restrict__ g_pxx,
    float* __restrict__ out)
{
    const float REG_FAC = (float)(1.6 * 1.6 - 1.0);   // REG_BASE**REG - 1

    __shared__ float stg[2][SG_TOT];
    __shared__ float sVx[NS], sVxx[NS * NS];
    __shared__ float fxV[144], fuV[48];
    __shared__ float sc_[6], r_[6], cinv_[6], cinr_[6];
    __shared__ float tQux[48], Quu2[16], Amat[16], Quh[4];
    __shared__ float LUm[16], rdg[4];
    __shared__ int   perm[4];
    __shared__ float kK[4 * 13];

    const int b    = blockIdx.x;
    const int lane = threadIdx.x;
    const unsigned FULL = 0xffffffffu;

    // ---- issue cp.async prefetch of one (b,t) stage into stg[bsel] ----
    auto issue_stage = [&](int bsel, long off) {
        float* d = stg[bsel];
        {
            const float4* s = (const float4*)(g_fxx + off * 1728);
            for (int i = lane; i < 432; i += 32) cpa16(d + SG_FXX + 4 * i, s + i);
        }
        {
            const float4* s = (const float4*)(g_fxu + off * 576);
            for (int i = lane; i < 144; i += 32) cpa16(d + SG_FXU + 4 * i, s + i);
        }
        {
            const float4* s = (const float4*)(g_fuu + off * 192);
            for (int i = lane; i < 48; i += 32) cpa16(d + SG_FUU + 4 * i, s + i);
        }
        {
            const float4* s = (const float4*)(g_fx + off * 144);
            for (int i = lane; i < 36; i += 32) cpa16(d + SG_FX + 4 * i, s + i);
        }
        {
            const float4* s = (const float4*)(g_qxx + off * 144);
            for (int i = lane; i < 36; i += 32) cpa16(d + SG_QXX + 4 * i, s + i);
        }
        {
            const float4* s = (const float4*)(g_fu + off * 48);
            if (lane < 12) cpa16(d + SG_FU + 4 * lane, s + lane);
        }
        {
            const float4* s = (const float4*)(g_qxu + off * 48);
            if (lane >= 12 && lane < 24) cpa16(d + SG_QXU + 4 * (lane - 12), s + (lane - 12));
        }
        {
            const float4* s = (const float4*)(g_cx + off * 72);
            if (lane < 18) cpa16(d + SG_CX + 4 * lane, s + lane);
        }
        {
            const float4* s = (const float4*)(g_cu + off * 24);
            if (lane >= 18 && lane < 24) cpa16(d + SG_CU + 4 * (lane - 18), s + (lane - 18));
        }
        {
            const float4* s = (const float4*)(g_quu + off * 16);
            if (lane >= 24 && lane < 28) cpa16(d + SG_QUU + 4 * (lane - 24), s + (lane - 24));
        }
        {
            const float4* s = (const float4*)(g_qx + off * 12);
            if (lane >= 28 && lane < 31) cpa16(d + SG_QX + 4 * (lane - 28), s + (lane - 28));
        }
        {
            const float4* s = (const float4*)(g_qu + off * 4);
            if (lane == 31) cpa16(d + SG_QU, s);
        }
        if (lane < 6)               cpa4(d + SG_C + lane,       g_c + off * 6 + lane);
        if (lane >= 6 && lane < 12) cpa4(d + SG_S + (lane - 6), g_s + off * 6 + (lane - 6));
        cpa_commit();
    };

    // ---- triangular pair decode (loop-invariant): pair p -> (i,j), i<=j ----
    int pi[3], pj[3];
    #pragma unroll
    for (int q = 0; q < 3; q++) {
        int p = lane + 32 * q;
        if (p < 78) {
            int i = 0, rem = p;
            while (rem >= 12 - i) { rem -= 12 - i; i++; }
            pi[q] = i; pj[q] = i + rem;
        } else { pi[q] = -1; pj[q] = -1; }
    }

    // ---- prologue: prefetch step T-1, init carry ----
    issue_stage(0, (long)b * NT + (NT - 1));
    if (lane < NS) sVx[lane] = g_px[b * NS + lane];
    for (int e = lane; e < 144; e += 32) sVxx[e] = g_pxx[b * 144 + e];

    float dv0 = 0.0f, dv1 = 0.0f, errq = 0.0f, errm = 0.0f;

    int buf = 0;
    for (int t = NT - 1; t >= 0; --t) {
        cpa_wait_all();
        __syncwarp();                                  // stage ready + prev carry writes visible

        if (t > 0) issue_stage(buf ^ 1, (long)b * NT + (t - 1));

        const float* S    = stg[buf];
        const float* Fxx  = S + SG_FXX;
        const float* Fxu  = S + SG_FXU;
        const float* Fuu  = S + SG_FUU;
        const float* Fx   = S + SG_FX;
        const float* Qxi2 = S + SG_QXX;
        const float* Fu   = S + SG_FU;
        const float* Qxui = S + SG_QXU;
        const float* Cx   = S + SG_CX;
        const float* Cu   = S + SG_CU;
        const float* Quui = S + SG_QUU;
        const float* Qxi  = S + SG_QX;
        const float* Qui  = S + SG_QU;
        const float* Cc   = S + SG_C;
        const float* Ssv  = S + SG_S;

        // register copy of Vx (reused many times this step)
        float sVxr[12];
        #pragma unroll
        for (int k = 0; k < 12; k++) sVxr[k] = sVx[k];

        // ================= Phase A: fxV, fuV, per-constraint scalars =================
        if (lane < NM) {
            float cm = Cc[lane], sm = Ssv[lane];
            float ci = 1.0f / cm;
            float rm = sm * cm + MU_C;
            cinv_[lane] = ci;
            r_[lane]    = rm;
            sc_[lane]   = sm / cm;
            cinr_[lane] = ci * rm;
        }
        #pragma unroll
        for (int q = 0; q < 5; q++) {
            int e = lane + 32 * q;
            if (e < 144) {
                int i = e / 12, j = e - 12 * i;
                float a = 0.0f;
                #pragma unroll
                for (int k = 0; k < NS; k++) a += Fx[k * 12 + i] * sVxx[k * 12 + j];
                fxV[e] = a;
            }
        }
        #pragma unroll
        for (int q = 0; q < 2; q++) {
            int e = lane + 32 * q;
            if (e < 48) {
                int u = e / 12, j = e - 12 * u;
                float a = 0.0f;
                #pragma unroll
                for (int k = 0; k < NS; k++) a += Fu[k * 4 + u] * sVxx[k * 12 + j];
                fuV[e] = a;
            }
        }
        __syncwarp();

        // ================= Phase B: Q matrices =================
        // Qxx2 pairs kept in registers (qA = element (i,j), qB = element (j,i))
        float qA[3], qB[3];
        #pragma unroll
        for (int q = 0; q < 3; q++) {
            int i = pi[q], j = pj[q];
            if (i >= 0) {
                float csc = 0.0f;
                #pragma unroll
                for (int m = 0; m < NM; m++) csc += Cx[m * 12 + i] * (sc_[m] * Cx[m * 12 + j]);
                float aij = Qxi2[i * 12 + j] - csc;
                float aji = Qxi2[j * 12 + i] - csc;
                #pragma unroll
                for (int k = 0; k < NS; k++) {
                    float w = sVxr[k];
                    aij += w * Fxx[k * 144 + i * 12 + j];
                    aji += w * Fxx[k * 144 + j * 12 + i];
                }
                #pragma unroll
                for (int k = 0; k < NS; k++) {
                    aij += fxV[i * 12 + k] * Fx[k * 12 + j];
                    aji += fxV[j * 12 + k] * Fx[k * 12 + i];
                }
                qA[q] = aij; qB[q] = aji;
            }
        }
        // tQux  (element f = u*12+x)
        #pragma unroll
        for (int q = 0; q < 2; q++) {
            int f = lane + 32 * q;
            if (f < 48) {
                int u = f / 12, x = f - 12 * u;
                float a = Qxui[x * 4 + u];
                #pragma unroll
                for (int k = 0; k < NS; k++) a += sVxr[k] * Fxu[k * 48 + x * 4 + u];
                #pragma unroll
                for (int k = 0; k < NS; k++) a += fxV[x * 12 + k] * Fu[k * 4 + u];
                #pragma unroll
                for (int m = 0; m < NM; m++) a -= Cu[m * 4 + u] * (sc_[m] * Cx[m * 12 + x]);
                tQux[f] = a;
            }
        }
        // Quu2 / Amat (lanes 0-15)
        if (lane < 16) {
            int u = lane / 4, w = lane - 4 * u;
            float a  = Quui[u * 4 + w];
            float b2 = Quui[w * 4 + u];
            #pragma unroll
            for (int k = 0; k < NS; k++) {
                float vv = sVxr[k];
                a  += vv * Fuu[k * 16 + u * 4 + w];
                b2 += vv * Fuu[k * 16 + w * 4 + u];
            }
            #pragma unroll
            for (int k = 0; k < NS; k++) {
                a  += fuV[u * 12 + k] * Fu[k * 4 + w];
                b2 += fuV[w * 12 + k] * Fu[k * 4 + u];
            }
            float sym = 0.5f * (a + b2);
            float csc = 0.0f;
            #pragma unroll
            for (int m = 0; m < NM; m++) csc += Cu[m * 4 + u] * (sc_[m] * Cu[m * 4 + w]);
            float q2 = sym - csc;
            Quu2[lane] = q2;
            Amat[lane] = q2 + Quui[u * 4 + w] * REG_FAC;
        }
        // Qx2 (lanes 0-11, kept in register)
        float Qx2r = 0.0f;
        if (lane < 12) {
            int x = lane;
            float a = Qxi[x];
            #pragma unroll
            for (int m = 0; m < NM; m++) a += Cx[m * 12 + x] * Ssv[m];
            #pragma unroll
            for (int k = 0; k < NS; k++) a += Fx[k * 12 + x] * sVxr[k];
            #pragma unroll
            for (int m = 0; m < NM; m++) a -= Cx[m * 12 + x] * cinr_[m];
            Qx2r = a;
        }
        // Quh (lanes 16-19)
        if (lane >= 16 && lane < 20) {
            int u = lane - 16;
            float a = Qui[u];
            #pragma unroll
            for (int m = 0; m < NM; m++) a += Cu[m * 4 + u] * Ssv[m];
            #pragma unroll
            for (int k = 0; k < NS; k++) a += Fu[k * 4 + u] * sVxr[k];
            #pragma unroll
            for (int m = 0; m < NM; m++) a -= Cu[m * 4 + u] * cinr_[m];
            Quh[u] = a;
        }
        __syncwarp();

        // ================= Phase C: 4x4 LU with partial pivoting, 13 RHS =================
        if (lane == 0) {
            float Al[4][4];
            #pragma unroll
            for (int i = 0; i < 4; i++)
                #pragma unroll
                for (int j = 0; j < 4; j++) Al[i][j] = Amat[i * 4 + j];
            int pm[4] = {0, 1, 2, 3};
            #pragma unroll
            for (int k = 0; k < 4; k++) {
                int p = k; float best = fabsf(Al[k][k]);
                for (int rr = k + 1; rr < 4; rr++) {
                    float v = fabsf(Al[rr][k]);
                    if (v > best) { best = v; p = rr; }
                }
                if (p != k) {
                    #pragma unroll
                    for (int cc = 0; cc < 4; cc++) {
                        float tmp = Al[k][cc]; Al[k][cc] = Al[p][cc]; Al[p][cc] = tmp;
                    }
                    int tpi = pm[k]; pm[k] = pm[p]; pm[p] = tpi;
                }
                float rd = 1.0f / Al[k][k];
                rdg[k] = rd;
                for (int rr = k + 1; rr < 4; rr++) {
                    float ml = Al[rr][k] * rd;
                    Al[rr][k] = ml;
                    for (int cc = k + 1; cc < 4; cc++) Al[rr][cc] -= ml * Al[k][cc];
                }
            }
            #pragma unroll
            for (int i = 0; i < 4; i++) {
                perm[i] = pm[i];
                #pragma unroll
                for (int j = 0; j < 4; j++) LUm[i * 4 + j] = Al[i][j];
            }
        }
        __syncwarp();
        if (lane < 13) {
            int col = lane;
            float bv[4];
            #pragma unroll
            for (int u = 0; u < 4; u++)
                bv[u] = (col == 0) ? Quh[u] : tQux[u * 12 + (col - 1)];
            float y[4];
            #pragma unroll
            for (int k = 0; k < 4; k++) {
                float a = bv[perm[k]];
                for (int j = 0; j < k; j++) a -= LUm[k * 4 + j] * y[j];
                y[k] = a;
            }
            float x[4];
            #pragma unroll
            for (int k = 3; k >= 0; k--) {
                float a = y[k];
                for (int j = k + 1; j < 4; j++) a -= LUm[k * 4 + j] * x[j];
                x[k] = a * rdg[k];
            }
            #pragma unroll
            for (int u = 0; u < 4; u++) kK[u * 13 + col] = -x[u];
        }
        __syncwarp();

        // ================= Phase D: outputs + new carry =================
        const long ot = (long)b * NT + t;
        // ku
        if (lane < 4) out[O_ku + ot * 4 + lane] = kK[lane * 13];
        // Ku
        #pragma unroll
        for (int q = 0; q < 2; q++) {
            int e = lane + 32 * q;
            if (e < 48) {
                int u = e / 12, x = e - 12 * u;
                out[O_Ku + ot * 48 + e] = kK[u * 13 + 1 + x];
            }
        }
        // ks (lanes 4-9)
        if (lane >= 4 && lane < 10) {
            int m = lane - 4;
            float cuku = 0.0f;
            #pragma unroll
            for (int u = 0; u < 4; u++) cuku += Cu[m * 4 + u] * kK[u * 13];
            out[O_ks + ot * 6 + m] = -cinv_[m] * (r_[m] + Ssv[m] * cuku);
        }
        // Ks
        #pragma unroll
        for (int q = 0; q < 3; q++) {
            int e = lane + 32 * q;
            if (e < 72) {
                int m = e / 12, x = e - 12 * m;
                float a = Cx[m * 12 + x];
                #pragma unroll
                for (int u = 0; u < 4; u++) a += Cu[m * 4 + u] * kK[u * 13 + 1 + x];
                out[O_Ks + ot * 72 + e] = -sc_[m] * a;
            }
        }
        // Vxx (pair-owned; uses register Qxx2 halves)
        #pragma unroll
        for (int q = 0; q < 3; q++) {
            int i = pi[q], j = pj[q];
            if (i >= 0) {
                float Kui[4], Kuj[4];
                #pragma unroll
                for (int u = 0; u < 4; u++) {
                    Kui[u] = kK[u * 13 + 1 + i];
                    Kuj[u] = kK[u * 13 + 1 + j];
                }
                float A1 = 0.0f, A2 = 0.0f;
                #pragma unroll
                for (int u = 0; u < 4; u++) {
                    A1 += tQux[u * 12 + i] * Kuj[u];
                    A2 += tQux[u * 12 + j] * Kui[u];
                }
                float Bq = 0.0f;
                #pragma unroll
                for (int u = 0; u < 4; u++) {
                    float tmp = 0.0f;
                    #pragma unroll
                    for (int w = 0; w < 4; w++) tmp += Kui[w] * Quu2[w * 4 + u];
                    Bq += tmp * Kuj[u];
                }
                float v = 0.5f * (qA[q] + qB[q]) + A1 + A2 + Bq;
                sVxx[i * 12 + j] = v;
                sVxx[j * 12 + i] = v;
            }
        }
        // Vx (lanes 0-11)
        if (lane < 12) {
            int x = lane;
            float a = Qx2r;
            #pragma unroll
            for (int u = 0; u < 4; u++) a += kK[u * 13 + 1 + x] * Quh[u];
            #pragma unroll
            for (int u = 0; u < 4; u++) {
                float kq = 0.0f;
                #pragma unroll
                for (int w = 0; w < 4; w++) kq += kK[w * 13 + 1 + x] * Quu2[w * 4 + u];
                a += kq * kK[u * 13];
            }
            #pragma unroll
            for (int u = 0; u < 4; u++) a += tQux[u * 12 + x] * kK[u * 13];
            sVx[x] = a;
        }
        // dV / err trackers (per-lane registers)
        if (lane == 20) {
            float a = 0.0f;
            #pragma unroll
            for (int u = 0; u < 4; u++) a += kK[u * 13] * Quh[u];
            dv0 += a;
        }
        if (lane == 21) {
            float a = 0.0f;
            #pragma unroll
            for (int u = 0; u < 4; u++)
                #pragma unroll
                for (int w = 0; w < 4; w++) a += kK[u * 13] * Quu2[u * 4 + w] * kK[w * 13];
            dv1 += 0.5f * a;
        }
        if (lane == 22) {
            #pragma unroll
            for (int u = 0; u < 4; u++) errq = fmaxf(errq, fabsf(Quh[u]));
        }
        if (lane == 23) {
            #pragma unroll
            for (int m = 0; m < NM; m++) errm = fmaxf(errm, fabsf(r_[m]));
        }

        buf ^= 1;
        // loop-top syncwarp (after cpa_wait) orders Phase-D shared writes before reuse
    }

    __syncwarp();
    // ---- epilogue ----
    if (lane == 20) out[O_dV + b * 2]     = dv0;
    if (lane == 21) out[O_dV + b * 2 + 1] = dv1;
    if (lane < NS)  out[O_Vx + b * NS + lane] = sVx[lane];
    for (int e = lane; e < 144; e += 32) out[O_Vxx + b * 144 + e] = sVxx[e];
    float ev = (lane == 22) ? errq : ((lane == 23) ? errm : 0.0f);
    #pragma unroll
    for (int o = 16; o > 0; o >>= 1) ev = fmaxf(ev, __shfl_xor_sync(FULL, ev, o));
    if (lane == 0) atomicMax((int*)(out + O_opt), __float_as_int(ev));
}

extern "C" void kernel_launch(void* const* d_in, const int* in_sizes, int n_in,
                              void* d_out, int out_size) {
    float* out = (float*)d_out;
    init_opt_kernel<<<1, 1>>>(out);
    ddp_backward_kernel<<<NB, 32>>>(
        (const float*)d_in[0],  (const float*)d_in[1],
        (const float*)d_in[2],  (const float*)d_in[3],
        (const float*)d_in[4],  (const float*)d_in[5],
        (const float*)d_in[6],  (const float*)d_in[7],
        (const float*)d_in[8],  (const float*)d_in[9],
        (const float*)d_in[10], (const float*)d_in[11],
        (const float*)d_in[12], (const float*)d_in[13],
        (const float*)d_in[14], (const float*)d_in[15],
        out);
}